// round 4
// baseline (speedup 1.0000x reference)
#include <cuda_runtime.h>
#include <math.h>

#define Bb   4
#define Ss   2048
#define Ee   512
#define Hh   8
#define HDd  64
#define BS   (Bb*Ss)            /* 8192 */
#define LDW  (2*Ee*Hh)          /* 8192 */
#define SCALE 0.044194173824159216f  /* 1/sqrt(512) */

/* ---- scratch (static device globals; no runtime allocation) ---- */
__device__ float g_M   [(size_t)Hh*Ee*Ee];   /* scale * Wq_h @ Wk_h^T, [h][c][c'] (8 MB)   */
__device__ float g_r   [Hh*Ee];              /* scale * Wk_h @ bq_h                        */
__device__ float g_beta[(size_t)Hh*BS];      /* beta[h][row] = x_row . g_r[h]              */
__device__ float g_t   [(size_t)Hh*BS*Ee];   /* t[h][row][e] = x @ M_h (134 MB)            */
__device__ float g_v   [(size_t)BS*Ee];      /* x @ Wv + bv                                */
__device__ float g_vals[(size_t)BS*Ee];      /* attention output, (b,s, h*64+d) layout     */

/* =====================================================================
 * M_h = SCALE * Wq_h @ Wk_h^T   (NT gemm over the contiguous e dim)
 * C[m,n] = SCALE * sum_k Wqk[m*LDW + h*1024 + k] * Wqk[n*LDW + h*1024+512 + k]
 * ===================================================================== */
__global__ __launch_bounds__(256) void mmat_kernel(const float* __restrict__ Wqk)
{
    const int h  = blockIdx.z;
    const int m0 = blockIdx.x * 128, n0 = blockIdx.y * 128;
    const int tid = threadIdx.x;
    const int tx = tid & 15, ty = tid >> 4;

    __shared__ float As[16][132];
    __shared__ float Bs[16][132];

    const float* Ab = Wqk + h * (2*Ee);        /* + c*LDW + e */
    const float* Bb2 = Wqk + h * (2*Ee) + Ee;

    float acc[8][8];
    #pragma unroll
    for (int i = 0; i < 8; i++)
        #pragma unroll
        for (int j = 0; j < 8; j++) acc[i][j] = 0.f;

    for (int kk = 0; kk < Ee; kk += 16) {
        #pragma unroll
        for (int i = 0; i < 2; i++) {
            int slot = tid + (i << 8);
            int m  = slot >> 2;
            int k4 = (slot & 3) << 2;
            float4 av = *(const float4*)(Ab  + (long)(m0 + m) * LDW + kk + k4);
            As[k4+0][m] = av.x; As[k4+1][m] = av.y; As[k4+2][m] = av.z; As[k4+3][m] = av.w;
            float4 bv = *(const float4*)(Bb2 + (long)(n0 + m) * LDW + kk + k4);
            Bs[k4+0][m] = bv.x; Bs[k4+1][m] = bv.y; Bs[k4+2][m] = bv.z; Bs[k4+3][m] = bv.w;
        }
        __syncthreads();
        #pragma unroll
        for (int k = 0; k < 16; k++) {
            float a[8], b[8];
            *(float4*)(a)     = *(const float4*)&As[k][ty*4];
            *(float4*)(a + 4) = *(const float4*)&As[k][ty*4 + 64];
            *(float4*)(b)     = *(const float4*)&Bs[k][tx*4];
            *(float4*)(b + 4) = *(const float4*)&Bs[k][tx*4 + 64];
            #pragma unroll
            for (int i = 0; i < 8; i++)
                #pragma unroll
                for (int j = 0; j < 8; j++) acc[i][j] += a[i] * b[j];
        }
        __syncthreads();
    }

    float* C = g_M + (size_t)h * Ee * Ee;
    #pragma unroll
    for (int rh = 0; rh < 2; rh++)
        #pragma unroll
        for (int i = 0; i < 4; i++) {
            int row = m0 + rh*64 + ty*4 + i;
            #pragma unroll
            for (int ch = 0; ch < 2; ch++) {
                float4 ov = make_float4(acc[rh*4+i][ch*4+0] * SCALE,
                                        acc[rh*4+i][ch*4+1] * SCALE,
                                        acc[rh*4+i][ch*4+2] * SCALE,
                                        acc[rh*4+i][ch*4+3] * SCALE);
                *(float4*)(C + (long)row * Ee + n0 + ch*64 + tx*4) = ov;
            }
        }
}

/* g_r[h*512 + c] = SCALE * sum_e Wqk[c*LDW + h*1024+512 + e] * bqk[h*1024 + e] */
__global__ void rvec_kernel(const float* __restrict__ Wqk, const float* __restrict__ bqk)
{
    int g = blockIdx.x * 256 + threadIdx.x;       /* 0..4095 */
    int h = g >> 9, c = g & 511;
    const float* wk = Wqk + (long)c * LDW + h * (2*Ee) + Ee;
    const float* bq = bqk + h * (2*Ee);
    float acc = 0.f;
    #pragma unroll 4
    for (int e = 0; e < Ee; e += 4) {
        acc += wk[e]*bq[e] + wk[e+1]*bq[e+1] + wk[e+2]*bq[e+2] + wk[e+3]*bq[e+3];
    }
    g_r[g] = acc * SCALE;
}

/* beta[h][row] = x_row . g_r[h]   (one warp per output) */
__global__ __launch_bounds__(256) void beta_kernel(const float* __restrict__ x)
{
    int w    = blockIdx.x * 8 + (threadIdx.x >> 5);   /* 0..65535 */
    int lane = threadIdx.x & 31;
    int h    = w >> 13;           /* /8192 */
    int row  = w & 8191;
    float acc = 0.f;
    #pragma unroll
    for (int i = 0; i < 4; i++) {
        int c = lane * 4 + i * 128;
        float4 xv = *(const float4*)(x   + (long)row * Ee + c);
        float4 rv = *(const float4*)(g_r + h * Ee + c);
        acc += xv.x*rv.x + xv.y*rv.y + xv.z*rv.z + xv.w*rv.w;
    }
    #pragma unroll
    for (int off = 16; off; off >>= 1) acc += __shfl_xor_sync(0xffffffffu, acc, off);
    if (!lane) g_beta[w] = acc;
}

/* =====================================================================
 * Generic fp32 SGEMM: C[z] = A @ B[z] (+ bias), 128x128x16 tiles, 8x8/thread
 * A row-major [M,K] (shared across z), B row-major [K,N], C row-major [M,N]
 * ===================================================================== */
__global__ __launch_bounds__(256) void sgemm_kernel(
    const float* __restrict__ A, const float* __restrict__ Bm,
    const float* __restrict__ bias, float* __restrict__ C,
    int Ndim, int Kdim, long strideB, long strideC)
{
    const int z = blockIdx.z;
    const float* Bz = Bm + (size_t)z * strideB;
    float*       Cz = C  + (size_t)z * strideC;
    const int m0 = blockIdx.x * 128, n0 = blockIdx.y * 128;
    const int tid = threadIdx.x;
    const int tx = tid & 15, ty = tid >> 4;

    __shared__ float As[16][132];
    __shared__ float Bs[16][128];

    float acc[8][8];
    #pragma unroll
    for (int i = 0; i < 8; i++)
        #pragma unroll
        for (int j = 0; j < 8; j++) acc[i][j] = 0.f;

    for (int kk = 0; kk < Kdim; kk += 16) {
        #pragma unroll
        for (int i = 0; i < 2; i++) {
            int slot = tid + (i << 8);
            int m  = slot >> 2;
            int k4 = (slot & 3) << 2;
            float4 av = *(const float4*)(A + (long)(m0 + m) * Kdim + kk + k4);
            As[k4+0][m] = av.x; As[k4+1][m] = av.y; As[k4+2][m] = av.z; As[k4+3][m] = av.w;
            int r  = slot >> 5;
            int c4 = (slot & 31) << 2;
            *(float4*)&Bs[r][c4] = *(const float4*)(Bz + (long)(kk + r) * Ndim + n0 + c4);
        }
        __syncthreads();
        #pragma unroll
        for (int k = 0; k < 16; k++) {
            float a[8], b[8];
            *(float4*)(a)     = *(const float4*)&As[k][ty*4];
            *(float4*)(a + 4) = *(const float4*)&As[k][ty*4 + 64];
            *(float4*)(b)     = *(const float4*)&Bs[k][tx*4];
            *(float4*)(b + 4) = *(const float4*)&Bs[k][tx*4 + 64];
            #pragma unroll
            for (int i = 0; i < 8; i++)
                #pragma unroll
                for (int j = 0; j < 8; j++) acc[i][j] += a[i] * b[j];
        }
        __syncthreads();
    }

    float b0[8] = {0,0,0,0,0,0,0,0};
    if (bias) {
        *(float4*)(b0)     = *(const float4*)(bias + n0 + tx*4);
        *(float4*)(b0 + 4) = *(const float4*)(bias + n0 + 64 + tx*4);
    }
    #pragma unroll
    for (int rh = 0; rh < 2; rh++)
        #pragma unroll
        for (int i = 0; i < 4; i++) {
            int row = m0 + rh*64 + ty*4 + i;
            #pragma unroll
            for (int ch = 0; ch < 2; ch++) {
                float4 ov = make_float4(acc[rh*4+i][ch*4+0] + b0[ch*4+0],
                                        acc[rh*4+i][ch*4+1] + b0[ch*4+1],
                                        acc[rh*4+i][ch*4+2] + b0[ch*4+2],
                                        acc[rh*4+i][ch*4+3] + b0[ch*4+3]);
                *(float4*)(Cz + (long)row * Ndim + n0 + ch*64 + tx*4) = ov;
            }
        }
}

/* =====================================================================
 * Fused flash attention (fp32, online softmax)
 * scores_eff[i,j] = t[h,row_i] . x[row_j]  + beta[h,row_j]   (scale folded)
 * 64x64 tile per CTA, 256 threads, 4x4 scores + 4x4 output per thread.
 * ===================================================================== */
__global__ __launch_bounds__(256) void attn_kernel(const float* __restrict__ x)
{
    const int qb = blockIdx.x, h = blockIdx.y, b = blockIdx.z;
    const int tid = threadIdx.x;
    const int tx = tid & 15, ty = tid >> 4;

    /* region1 (qs[32][68] + ks[32][68]) is reused as Psm[64][64]; Vsm separate */
    __shared__ float sm[2*32*68 + 64*64];
    float* qs  = sm;                 /* [32][68] transposed: qs[e][i] */
    float* ks  = sm + 32*68;         /* [32][68] transposed: ks[e][j] */
    float* Psm = sm;                 /* [64][64] */
    float* Vsm = sm + 2*32*68;       /* [64][64] */

    const long tq0 = ((long)h * BS + (long)b * Ss + qb * 64);  /* t row base      */
    const long xk0 = ((long)b * Ss);                           /* x/g_v row base  */

    float o[4][4];
    float mrow[4], lrow[4];
    #pragma unroll
    for (int r = 0; r < 4; r++) {
        mrow[r] = -1e30f; lrow[r] = 0.f;
        #pragma unroll
        for (int c = 0; c < 4; c++) o[r][c] = 0.f;
    }

    for (int kb = 0; kb < Ss/64; kb++) {
        float s[4][4];
        #pragma unroll
        for (int r = 0; r < 4; r++)
            #pragma unroll
            for (int c = 0; c < 4; c++) s[r][c] = 0.f;

        /* ---- scores: contract over E=512 in chunks of 32 ---- */
        for (int ec = 0; ec < Ee; ec += 32) {
            #pragma unroll
            for (int i = 0; i < 2; i++) {
                int slot = tid + (i << 8);
                int row = slot >> 3;
                int e4  = (slot & 7) << 2;
                float4 qv = *(const float4*)(g_t + (tq0 + row) * Ee + ec + e4);
                qs[(e4+0)*68 + row] = qv.x; qs[(e4+1)*68 + row] = qv.y;
                qs[(e4+2)*68 + row] = qv.z; qs[(e4+3)*68 + row] = qv.w;
                float4 kv = *(const float4*)(x + (xk0 + kb*64 + row) * Ee + ec + e4);
                ks[(e4+0)*68 + row] = kv.x; ks[(e4+1)*68 + row] = kv.y;
                ks[(e4+2)*68 + row] = kv.z; ks[(e4+3)*68 + row] = kv.w;
            }
            __syncthreads();
            #pragma unroll
            for (int e = 0; e < 32; e++) {
                float qa[4], ka[4];
                *(float4*)qa = *(const float4*)&qs[e*68 + ty*4];
                *(float4*)ka = *(const float4*)&ks[e*68 + tx*4];
                #pragma unroll
                for (int r = 0; r < 4; r++)
                    #pragma unroll
                    for (int c = 0; c < 4; c++) s[r][c] += qa[r] * ka[c];
            }
            __syncthreads();
        }

        /* ---- V tile (independent of softmax, load early) ---- */
        #pragma unroll
        for (int i = 0; i < 4; i++) {
            int slot = tid + (i << 8);
            int j  = slot >> 4;
            int d4 = (slot & 15) << 2;
            *(float4*)&Vsm[j*64 + d4] =
                *(const float4*)(g_v + (xk0 + kb*64 + j) * Ee + h*HDd + d4);
        }

        /* ---- online softmax ---- */
        float4 bt = *(const float4*)(g_beta + (long)h * BS + b * Ss + kb*64 + tx*4);
        float bj[4] = {bt.x, bt.y, bt.z, bt.w};
        #pragma unroll
        for (int r = 0; r < 4; r++) {
            float mx = -1e30f;
            #pragma unroll
            for (int c = 0; c < 4; c++) { s[r][c] += bj[c]; mx = fmaxf(mx, s[r][c]); }
            #pragma unroll
            for (int off = 8; off; off >>= 1)
                mx = fmaxf(mx, __shfl_xor_sync(0xffffffffu, mx, off, 16));
            float mn   = fmaxf(mrow[r], mx);
            float corr = __expf(mrow[r] - mn);
            mrow[r] = mn;
            float p[4], ps = 0.f;
            #pragma unroll
            for (int c = 0; c < 4; c++) { p[c] = __expf(s[r][c] - mn); ps += p[c]; }
            #pragma unroll
            for (int off = 8; off; off >>= 1)
                ps += __shfl_xor_sync(0xffffffffu, ps, off, 16);
            lrow[r] = lrow[r] * corr + ps;
            #pragma unroll
            for (int c = 0; c < 4; c++) o[r][c] *= corr;
            *(float4*)&Psm[(ty*4 + r)*64 + tx*4] = make_float4(p[0], p[1], p[2], p[3]);
        }
        __syncthreads();

        /* ---- O += P @ V ---- */
        #pragma unroll
        for (int jc = 0; jc < 64; jc += 4) {
            float pv[4][4], vb[4][4];
            #pragma unroll
            for (int r = 0; r < 4; r++)
                *(float4*)pv[r] = *(const float4*)&Psm[(ty*4 + r)*64 + jc];
            #pragma unroll
            for (int jj = 0; jj < 4; jj++)
                *(float4*)vb[jj] = *(const float4*)&Vsm[(jc + jj)*64 + tx*4];
            #pragma unroll
            for (int r = 0; r < 4; r++)
                #pragma unroll
                for (int jj = 0; jj < 4; jj++)
                    #pragma unroll
                    for (int c = 0; c < 4; c++)
                        o[r][c] += pv[r][jj] * vb[jj][c];
        }
        __syncthreads();
    }

    /* ---- epilogue: vals[b, s, h*64 + d] = o / l ---- */
    #pragma unroll
    for (int r = 0; r < 4; r++) {
        float inv = 1.0f / lrow[r];
        float4 ov = make_float4(o[r][0]*inv, o[r][1]*inv, o[r][2]*inv, o[r][3]*inv);
        *(float4*)(g_vals + ((long)b * Ss + qb*64 + ty*4 + r) * Ee + h*HDd + tx*4) = ov;
    }
}

/* ===================================================================== */
extern "C" void kernel_launch(void* const* d_in, const int* in_sizes, int n_in,
                              void* d_out, int out_size)
{
    const float* x   = (const float*)d_in[0];
    const float* Wqk = (const float*)d_in[1];
    const float* bqk = (const float*)d_in[2];
    const float* Wv  = (const float*)d_in[3];
    const float* bv  = (const float*)d_in[4];
    const float* Wo  = (const float*)d_in[5];
    const float* bo  = (const float*)d_in[6];
    float* out = (float*)d_out;

    void *pM, *pT, *pV, *pVals;
    cudaGetSymbolAddress(&pM,    g_M);
    cudaGetSymbolAddress(&pT,    g_t);
    cudaGetSymbolAddress(&pV,    g_v);
    cudaGetSymbolAddress(&pVals, g_vals);

    /* 1. M_h = scale * Wq_h Wk_h^T ; r_h = scale * Wk_h bq_h ; beta */
    mmat_kernel<<<dim3(4, 4, 8), 256>>>(Wqk);
    rvec_kernel<<<16, 256>>>(Wqk, bqk);
    beta_kernel<<<8192, 256>>>(x);

    /* 2. t[h] = x @ M_h  (batched over h) */
    sgemm_kernel<<<dim3(64, 4, 8), 256>>>(
        x, (const float*)pM, nullptr, (float*)pT,
        Ee, Ee, (long)Ee * Ee, (long)BS * Ee);

    /* 3. v = x @ Wv + bv */
    sgemm_kernel<<<dim3(64, 4, 1), 256>>>(
        x, Wv, bv, (float*)pV, Ee, Ee, 0, 0);

    /* 4. fused flash attention -> g_vals (b, s, h*64+d) */
    attn_kernel<<<dim3(Ss/64, Hh, Bb), 256>>>(x);

    /* 5. out = vals @ Wo + bo */
    sgemm_kernel<<<dim3(64, 4, 1), 256>>>(
        (const float*)pVals, Wo, bo, out, Ee, Ee, 0, 0);
}